// round 3
// baseline (speedup 1.0000x reference)
#include <cuda_runtime.h>

typedef unsigned long long ull;

#define X7    (7*1048576)      // x[7] offset (floats)
#define W7OFF (7*8*4096)       // weights[7] offset (floats)

// Scratch (device globals — no allocations allowed)
__device__ float g_uhl[8*16384*64];  // [j][b][e] 32MB
__device__ float g_n2[8*16384];      // [j][b]
__device__ float g_um[512];          // sum_b u[b,i,d]
__device__ float g_uhm[4096];        // [i][j][e]
__device__ float g_B[64];
__device__ float g_t[512];           // [j][d]
__device__ float g_c[8];             // final-iteration c_j

__device__ __forceinline__ void fma2(ull &acc, ull a, ull b) {
    asm("fma.rn.f32x2 %0, %1, %2, %0;" : "+l"(acc) : "l"(a), "l"(b));
}
__device__ __forceinline__ float2 unpack2(ull v) {
    unsigned lo, hi;
    asm("mov.b64 {%0, %1}, %2;" : "=r"(lo), "=r"(hi) : "l"(v));
    return make_float2(__uint_as_float(lo), __uint_as_float(hi));
}
__device__ __forceinline__ float squash_scal(float cj, float n2v) {
    float s2 = cj*cj*n2v;
    return cj*s2 / ((1.f+s2)*sqrtf(s2+1e-9f));
}
// x[7] memory row for u-row b:  u[b,7,d] = x[7, b&31, b>>5, d]
__device__ __forceinline__ int xrow(int b) {
    return (b & 31)*512 + (b >> 5);
}

__global__ void k_init() {
    int t = threadIdx.x;           // 512
    g_t[t] = 0.f; g_um[t] = 0.f;
    if (t < 64) g_B[t] = 0.f;
}

// sum over all 16384 rows of x[i] -> g_um[i*64+d]  (order-invariant)
__global__ void k_umean(const float* __restrict__ x) {
    __shared__ float red[4][64];
    int i = blockIdx.y, t = threadIdx.x, d = t & 63, g = t >> 6;
    const float* xp = x + i*1048576 + (blockIdx.x*1024 + g*256)*64 + d;
    float s = 0.f;
    #pragma unroll 4
    for (int m = 0; m < 256; m++) s += xp[m*64];
    red[g][d] = s;
    __syncthreads();
    if (t < 64) atomicAdd(&g_um[i*64+t], red[0][t]+red[1][t]+red[2][t]+red[3][t]);
}

// uhm[i,j,e] = sum_d W[i,j,d,e] * umean[i,d]
__global__ void k_uhm(const float* __restrict__ w) {
    __shared__ float um[512];
    int t = threadIdx.x;           // 256
    um[t]     = g_um[t]     * (1.f/16384.f);
    um[t+256] = g_um[t+256] * (1.f/16384.f);
    __syncthreads();
    #pragma unroll
    for (int o = 0; o < 16; o++) {
        int idx = t + 256*o;
        int i = idx >> 9, e = idx & 63;
        int ij = idx >> 6;         // i*8+j
        const float* wp = w + ij*4096 + e;
        const float* up = um + i*64;
        float s = 0.f;
        #pragma unroll 8
        for (int d = 0; d < 64; d++) s += wp[d*64] * up[d];
        g_uhm[idx] = s;
    }
}

// uhl[j,b,e] = sum_d u[b,7,d]*W7[j,d,e]; n2[j,b] = sum_e uhl^2
__global__ __launch_bounds__(256) void k_gemm(const float* __restrict__ x,
                                              const float* __restrict__ w) {
    __shared__ float2 xs[64*32];   // [d][rowpair] 16KB
    __shared__ float2 ws2[64*64];  // [d][e] value-duplicated 32KB
    int t = threadIdx.x;
    int p0 = blockIdx.x * 64;      // b-block base

    {   // load + transpose 64 u-rows (gather from permuted x layout)
        int rp_ = t & 31, d8 = t >> 5;
        int bA = p0 + 2*rp_, bB = bA + 1;
        const float* pa = x + X7 + xrow(bA)*64 + d8*8;
        const float* pb = x + X7 + xrow(bB)*64 + d8*8;
        float4 a0 = *(const float4*)pa, a1 = *(const float4*)(pa+4);
        float4 b0 = *(const float4*)pb, b1 = *(const float4*)(pb+4);
        float av[8] = {a0.x,a0.y,a0.z,a0.w,a1.x,a1.y,a1.z,a1.w};
        float bv[8] = {b0.x,b0.y,b0.z,b0.w,b1.x,b1.y,b1.z,b1.w};
        #pragma unroll
        for (int i = 0; i < 8; i++)
            xs[(d8*8+i)*32 + rp_] = make_float2(av[i], bv[i]);
    }

    int rp = t >> 3, c0 = (t & 7) * 8;
    const float* W7p = w + W7OFF;

    for (int j = 0; j < 8; j++) {
        __syncthreads();
        #pragma unroll
        for (int k = 0; k < 4; k++) {   // 4096 floats -> duplicated float2
            int idx = t + 256*k;
            float4 v = *(const float4*)(W7p + j*4096 + idx*4);
            float4* wd = (float4*)&ws2[idx*4];
            wd[0] = make_float4(v.x,v.x,v.y,v.y);
            wd[1] = make_float4(v.z,v.z,v.w,v.w);
        }
        __syncthreads();

        ull acc[8] = {0,0,0,0,0,0,0,0};
        #pragma unroll 2
        for (int d = 0; d < 64; d++) {
            ull xr = *(const ull*)&xs[d*32 + rp];
            const longlong2* wp = (const longlong2*)&ws2[d*64 + c0];
            #pragma unroll
            for (int k = 0; k < 4; k++) {
                longlong2 q = wp[k];
                fma2(acc[2*k],   xr, (ull)q.x);
                fma2(acc[2*k+1], xr, (ull)q.y);
            }
        }

        float2 v[8];
        #pragma unroll
        for (int i = 0; i < 8; i++) v[i] = unpack2(acc[i]);

        float* oa = g_uhl + j*1048576 + (p0 + 2*rp)*64 + c0;
        *(float4*)oa      = make_float4(v[0].x,v[1].x,v[2].x,v[3].x);
        *(float4*)(oa+4)  = make_float4(v[4].x,v[5].x,v[6].x,v[7].x);
        *(float4*)(oa+64) = make_float4(v[0].y,v[1].y,v[2].y,v[3].y);
        *(float4*)(oa+68) = make_float4(v[4].y,v[5].y,v[6].y,v[7].y);

        float sA = 0.f, sB = 0.f;
        #pragma unroll
        for (int i = 0; i < 8; i++) { sA += v[i].x*v[i].x; sB += v[i].y*v[i].y; }
        #pragma unroll
        for (int off = 1; off < 8; off <<= 1) {
            sA += __shfl_xor_sync(~0u, sA, off);
            sB += __shfl_xor_sync(~0u, sB, off);
        }
        if ((t & 7) == 0) {
            g_n2[j*16384 + p0 + 2*rp]     = sA;
            g_n2[j*16384 + p0 + 2*rp + 1] = sB;
        }
    }
}

// one routing reduction: c=softmax(B)[7,:]; t[j,d] += scal(b,j)*u[b,7,d]
__global__ __launch_bounds__(256) void k_route1(const float* __restrict__ x) {
    __shared__ float c_s[8];
    __shared__ float scal_s[256*8];
    __shared__ float red[4][512];
    int t = threadIdx.x;
    if (t < 8) {
        float m = g_B[t];
        #pragma unroll
        for (int i = 1; i < 8; i++) m = fmaxf(m, g_B[i*8+t]);
        float sum = 0.f, e7 = 0.f;
        #pragma unroll
        for (int i = 0; i < 8; i++) {
            float e = expf(g_B[i*8+t] - m);
            sum += e; if (i == 7) e7 = e;
        }
        c_s[t] = e7/sum;
    }
    __syncthreads();
    int p0 = blockIdx.x * 256;
    {
        int b = p0 + t;
        #pragma unroll
        for (int j = 0; j < 8; j++)
            scal_s[t*8+j] = squash_scal(c_s[j], g_n2[j*16384 + b]);
    }
    __syncthreads();
    int d = t & 63, g = t >> 6;
    float acc[8] = {0,0,0,0,0,0,0,0};
    for (int m = 0; m < 64; m++) {
        int r = g*64 + m;
        int b = p0 + r;
        float xv = x[X7 + xrow(b)*64 + d];
        #pragma unroll
        for (int j = 0; j < 8; j++) acc[j] += scal_s[r*8+j] * xv;
    }
    #pragma unroll
    for (int j = 0; j < 8; j++) red[g][j*64+d] = acc[j];
    __syncthreads();
    #pragma unroll
    for (int o = 0; o < 2; o++) {
        int idx = t + 256*o;
        atomicAdd(&g_t[idx], red[0][idx]+red[1][idx]+red[2][idx]+red[3][idx]);
    }
}

// vmean[j,e] = (1/16384)*sum_d W7[j,d,e]*t[j,d]; B += uhm.vmean; g_c=softmax(B)[7]
__global__ void k_route2(const float* __restrict__ w) {
    __shared__ float ts[512], vm[512];
    int t = threadIdx.x;           // 256
    ts[t] = g_t[t]; ts[t+256] = g_t[t+256];
    __syncthreads();
    g_t[t] = 0.f; g_t[t+256] = 0.f;
    const float* W7p = w + W7OFF;
    #pragma unroll
    for (int o = 0; o < 2; o++) {
        int idx = t + 256*o, j = idx >> 6, e = idx & 63;
        const float* wp = W7p + j*4096 + e;
        const float* tp = ts + j*64;
        float s = 0.f;
        #pragma unroll 8
        for (int d = 0; d < 64; d++) s += wp[d*64] * tp[d];
        vm[idx] = s * (1.f/16384.f);
    }
    __syncthreads();
    if (t < 64) {
        int j = t & 7;
        float s = 0.f;
        #pragma unroll 8
        for (int e = 0; e < 64; e++) s += g_uhm[t*64 + e] * vm[j*64 + e];
        g_B[t] += s;
    }
    __syncthreads();
    if (t < 8) {
        float m = g_B[t];
        #pragma unroll
        for (int i = 1; i < 8; i++) m = fmaxf(m, g_B[i*8+t]);
        float sum = 0.f, e7 = 0.f;
        #pragma unroll
        for (int i = 0; i < 8; i++) {
            float e = expf(g_B[i*8+t] - m);
            sum += e; if (i == 7) e7 = e;
        }
        g_c[t] = e7/sum;
    }
}

// out[j,b,e] = scal3(j,b) * uhl[j,b,e]  (pure stream; output position == b)
__global__ void k_out(float* __restrict__ out) {
    __shared__ float scal_s[128];
    int j = blockIdx.y, p0 = blockIdx.x * 128, t = threadIdx.x;
    if (t < 128) scal_s[t] = squash_scal(g_c[j], g_n2[j*16384 + p0 + t]);
    __syncthreads();
    const float4* src = (const float4*)(g_uhl + j*1048576 + p0*64);
    float4* dst = (float4*)(out + j*1048576 + p0*64);
    #pragma unroll
    for (int k = 0; k < 8; k++) {
        int idx = k*256 + t;       // 2048 float4
        float4 v = src[idx];
        float s = scal_s[idx >> 4];
        v.x *= s; v.y *= s; v.z *= s; v.w *= s;
        dst[idx] = v;
    }
}

extern "C" void kernel_launch(void* const* d_in, const int* in_sizes, int n_in,
                              void* d_out, int out_size) {
    const float* x = (const float*)d_in[0];
    const float* w = (const float*)d_in[1];
    float* out = (float*)d_out;
    k_init<<<1, 512>>>();
    k_umean<<<dim3(16, 8), 256>>>(x);
    k_uhm<<<1, 256>>>(w);
    k_gemm<<<256, 256>>>(x, w);
    k_route1<<<64, 256>>>(x);
    k_route2<<<1, 256>>>(w);
    k_route1<<<64, 256>>>(x);
    k_route2<<<1, 256>>>(w);
    k_out<<<dim3(128, 8), 256>>>(out);
}

// round 4
// speedup vs baseline: 1.3743x; 1.3743x over previous
#include <cuda_runtime.h>

typedef unsigned long long ull;

#define X7    (7*1048576)      // x[7] offset (floats)
#define W7OFF (7*8*4096)       // weights[7] offset (floats)

// Scratch (device globals — no allocations allowed)
__device__ float g_uhl[8*16384*64];  // [j][b][e] 32MB
__device__ float g_n2[8*16384];      // [j][b]
__device__ float g_um[512];          // sum_b u[b,i,d]
__device__ float g_uhm[4096];        // [i][j][e]
__device__ float g_B[64];
__device__ float g_t[512];           // [j][d]
__device__ float g_c[8];             // final-iteration c_j

__device__ __forceinline__ void fma2(ull &acc, ull a, ull b) {
    asm("fma.rn.f32x2 %0, %1, %2, %0;" : "+l"(acc) : "l"(a), "l"(b));
}
__device__ __forceinline__ float2 unpack2(ull v) {
    unsigned lo, hi;
    asm("mov.b64 {%0, %1}, %2;" : "=r"(lo), "=r"(hi) : "l"(v));
    return make_float2(__uint_as_float(lo), __uint_as_float(hi));
}
__device__ __forceinline__ float squash_scal(float cj, float n2v) {
    float s2 = cj*cj*n2v;
    return cj*s2 / ((1.f+s2)*sqrtf(s2+1e-9f));
}
// x[7] memory row for u-row b:  u[b,7,d] = x[7, b&31, b>>5, d]
__device__ __forceinline__ int xrow(int b) {
    return (b & 31)*512 + (b >> 5);
}

__global__ void k_init() {
    int t = threadIdx.x;           // 512
    g_t[t] = 0.f; g_um[t] = 0.f;
    if (t < 64) g_B[t] = 0.f;
}

// sum over all 16384 rows of x[i] -> g_um[i*64+d]  (order-invariant)
__global__ void k_umean(const float* __restrict__ x) {
    __shared__ float red[4][64];
    int i = blockIdx.y, t = threadIdx.x, d = t & 63, g = t >> 6;
    const float* xp = x + i*1048576 + (blockIdx.x*1024 + g*256)*64 + d;
    float s = 0.f;
    #pragma unroll 4
    for (int m = 0; m < 256; m++) s += xp[m*64];
    red[g][d] = s;
    __syncthreads();
    if (t < 64) atomicAdd(&g_um[i*64+t], red[0][t]+red[1][t]+red[2][t]+red[3][t]);
}

// uhm[i,j,e] = sum_d W[i,j,d,e] * umean[i,d]
__global__ void k_uhm(const float* __restrict__ w) {
    __shared__ float um[512];
    int t = threadIdx.x;           // 256
    um[t]     = g_um[t]     * (1.f/16384.f);
    um[t+256] = g_um[t+256] * (1.f/16384.f);
    __syncthreads();
    #pragma unroll
    for (int o = 0; o < 16; o++) {
        int idx = t + 256*o;
        int i = idx >> 9, e = idx & 63;
        int ij = idx >> 6;         // i*8+j
        const float* wp = w + ij*4096 + e;
        const float* up = um + i*64;
        float s = 0.f;
        #pragma unroll 8
        for (int d = 0; d < 64; d++) s += wp[d*64] * up[d];
        g_uhm[idx] = s;
    }
}

// uhl[j,b,e] = sum_d u[b,7,d]*W7[j,d,e]; n2[j,b] = sum_e uhl^2
// 128 threads, 64 rows/block, grid 256 (all blocks co-resident: 48KB smem).
// Thread: 2 row-pairs x 8 cols -> 16 independent f32x2 chains.
__global__ __launch_bounds__(128) void k_gemm(const float* __restrict__ x,
                                              const float* __restrict__ w) {
    __shared__ float2 xs[64*32];   // [d][rp] row-pair packed, 16KB
    __shared__ float2 ws2[64*64];  // [d][e] value-duplicated, 32KB
    int t = threadIdx.x;           // 128
    int p0 = blockIdx.x * 64;      // b-block base

    {   // load + transpose 64 u-rows (gather from permuted x layout)
        int rp_ = t & 31, q = t >> 5;      // q: d-chunk of 16
        int bA = p0 + 2*rp_, bB = bA + 1;
        const float* pa = x + X7 + xrow(bA)*64 + q*16;
        const float* pb = x + X7 + xrow(bB)*64 + q*16;
        #pragma unroll
        for (int i = 0; i < 4; i++) {
            float4 a = *(const float4*)(pa + 4*i);
            float4 b = *(const float4*)(pb + 4*i);
            int d0 = q*16 + 4*i;
            xs[(d0+0)*32 + rp_] = make_float2(a.x, b.x);
            xs[(d0+1)*32 + rp_] = make_float2(a.y, b.y);
            xs[(d0+2)*32 + rp_] = make_float2(a.z, b.z);
            xs[(d0+3)*32 + rp_] = make_float2(a.w, b.w);
        }
    }

    int cg = t & 7, rq = t >> 3;   // cg: 8 cols each; rq: 16 groups x 2 rp
    const float* W7p = w + W7OFF;

    for (int j = 0; j < 8; j++) {
        __syncthreads();
        #pragma unroll
        for (int k = 0; k < 8; k++) {   // 4096 floats -> duplicated float2
            int idx = t + 128*k;
            float4 v = *(const float4*)(W7p + j*4096 + idx*4);
            float4* wd = (float4*)&ws2[idx*4];
            wd[0] = make_float4(v.x,v.x,v.y,v.y);
            wd[1] = make_float4(v.z,v.z,v.w,v.w);
        }
        __syncthreads();

        ull a0[8] = {0,0,0,0,0,0,0,0};   // row-pair 2rq
        ull a1[8] = {0,0,0,0,0,0,0,0};   // row-pair 2rq+1
        #pragma unroll 8
        for (int d = 0; d < 64; d++) {
            ulonglong2 xp = *(const ulonglong2*)&xs[d*32 + 2*rq];
            const ulonglong2* wp = (const ulonglong2*)&ws2[d*64 + cg*8];
            #pragma unroll
            for (int k = 0; k < 4; k++) {
                ulonglong2 q = wp[k];
                fma2(a0[2*k],   xp.x, q.x);
                fma2(a0[2*k+1], xp.x, q.y);
                fma2(a1[2*k],   xp.y, q.x);
                fma2(a1[2*k+1], xp.y, q.y);
            }
        }

        #pragma unroll
        for (int rr = 0; rr < 2; rr++) {
            ull* acc = rr ? a1 : a0;
            float2 v[8];
            #pragma unroll
            for (int i = 0; i < 8; i++) v[i] = unpack2(acc[i]);

            int bA = p0 + 4*rq + 2*rr;   // rows bA, bA+1
            float* oa = g_uhl + j*1048576 + bA*64 + cg*8;
            *(float4*)oa      = make_float4(v[0].x,v[1].x,v[2].x,v[3].x);
            *(float4*)(oa+4)  = make_float4(v[4].x,v[5].x,v[6].x,v[7].x);
            *(float4*)(oa+64) = make_float4(v[0].y,v[1].y,v[2].y,v[3].y);
            *(float4*)(oa+68) = make_float4(v[4].y,v[5].y,v[6].y,v[7].y);

            float sA = 0.f, sB = 0.f;
            #pragma unroll
            for (int i = 0; i < 8; i++) { sA += v[i].x*v[i].x; sB += v[i].y*v[i].y; }
            #pragma unroll
            for (int off = 1; off < 8; off <<= 1) {
                sA += __shfl_xor_sync(~0u, sA, off);
                sB += __shfl_xor_sync(~0u, sB, off);
            }
            if (cg == 0) {
                g_n2[j*16384 + bA]     = sA;
                g_n2[j*16384 + bA + 1] = sB;
            }
        }
    }
}

// one routing reduction: c=softmax(B)[7,:]; t[j,d] += scal(b,j)*u[b,7,d]
__global__ __launch_bounds__(256) void k_route1(const float* __restrict__ x) {
    __shared__ float c_s[8];
    __shared__ float scal_s[256*8];
    __shared__ float red[4][512];
    int t = threadIdx.x;
    if (t < 8) {
        float m = g_B[t];
        #pragma unroll
        for (int i = 1; i < 8; i++) m = fmaxf(m, g_B[i*8+t]);
        float sum = 0.f, e7 = 0.f;
        #pragma unroll
        for (int i = 0; i < 8; i++) {
            float e = expf(g_B[i*8+t] - m);
            sum += e; if (i == 7) e7 = e;
        }
        c_s[t] = e7/sum;
    }
    __syncthreads();
    int p0 = blockIdx.x * 256;
    {
        int b = p0 + t;
        #pragma unroll
        for (int j = 0; j < 8; j++)
            scal_s[t*8+j] = squash_scal(c_s[j], g_n2[j*16384 + b]);
    }
    __syncthreads();
    int d = t & 63, g = t >> 6;
    float acc[8] = {0,0,0,0,0,0,0,0};
    for (int m = 0; m < 64; m++) {
        int r = g*64 + m;
        int b = p0 + r;
        float xv = x[X7 + xrow(b)*64 + d];
        #pragma unroll
        for (int j = 0; j < 8; j++) acc[j] += scal_s[r*8+j] * xv;
    }
    #pragma unroll
    for (int j = 0; j < 8; j++) red[g][j*64+d] = acc[j];
    __syncthreads();
    #pragma unroll
    for (int o = 0; o < 2; o++) {
        int idx = t + 256*o;
        atomicAdd(&g_t[idx], red[0][idx]+red[1][idx]+red[2][idx]+red[3][idx]);
    }
}

// vmean[j,e] = (1/16384)*sum_d W7[j,d,e]*t[j,d]; B += uhm.vmean; g_c=softmax(B)[7]
__global__ void k_route2(const float* __restrict__ w) {
    __shared__ float ts[512], vm[512];
    int t = threadIdx.x;           // 256
    ts[t] = g_t[t]; ts[t+256] = g_t[t+256];
    __syncthreads();
    g_t[t] = 0.f; g_t[t+256] = 0.f;
    const float* W7p = w + W7OFF;
    #pragma unroll
    for (int o = 0; o < 2; o++) {
        int idx = t + 256*o, j = idx >> 6, e = idx & 63;
        const float* wp = W7p + j*4096 + e;
        const float* tp = ts + j*64;
        float s = 0.f;
        #pragma unroll 8
        for (int d = 0; d < 64; d++) s += wp[d*64] * tp[d];
        vm[idx] = s * (1.f/16384.f);
    }
    __syncthreads();
    if (t < 64) {
        int j = t & 7;
        float s = 0.f;
        #pragma unroll 8
        for (int e = 0; e < 64; e++) s += g_uhm[t*64 + e] * vm[j*64 + e];
        g_B[t] += s;
    }
    __syncthreads();
    if (t < 8) {
        float m = g_B[t];
        #pragma unroll
        for (int i = 1; i < 8; i++) m = fmaxf(m, g_B[i*8+t]);
        float sum = 0.f, e7 = 0.f;
        #pragma unroll
        for (int i = 0; i < 8; i++) {
            float e = expf(g_B[i*8+t] - m);
            sum += e; if (i == 7) e7 = e;
        }
        g_c[t] = e7/sum;
    }
}

// out[j,b,e] = scal3(j,b) * uhl[j,b,e]  (pure stream; output position == b)
__global__ void k_out(float* __restrict__ out) {
    __shared__ float scal_s[128];
    int j = blockIdx.y, p0 = blockIdx.x * 128, t = threadIdx.x;
    if (t < 128) scal_s[t] = squash_scal(g_c[j], g_n2[j*16384 + p0 + t]);
    __syncthreads();
    const float4* src = (const float4*)(g_uhl + j*1048576 + p0*64);
    float4* dst = (float4*)(out + j*1048576 + p0*64);
    #pragma unroll
    for (int k = 0; k < 8; k++) {
        int idx = k*256 + t;       // 2048 float4
        float4 v = src[idx];
        float s = scal_s[idx >> 4];
        v.x *= s; v.y *= s; v.z *= s; v.w *= s;
        dst[idx] = v;
    }
}

extern "C" void kernel_launch(void* const* d_in, const int* in_sizes, int n_in,
                              void* d_out, int out_size) {
    const float* x = (const float*)d_in[0];
    const float* w = (const float*)d_in[1];
    float* out = (float*)d_out;
    k_init<<<1, 512>>>();
    k_umean<<<dim3(16, 8), 256>>>(x);
    k_uhm<<<1, 256>>>(w);
    k_gemm<<<256, 128>>>(x, w);
    k_route1<<<64, 256>>>(x);
    k_route2<<<1, 256>>>(w);
    k_route1<<<64, 256>>>(x);
    k_route2<<<1, 256>>>(w);
    k_out<<<dim3(128, 8), 256>>>(out);
}

// round 5
// speedup vs baseline: 2.2880x; 1.6649x over previous
#include <cuda_runtime.h>

typedef unsigned long long ull;

#define X7    (7*1048576)      // x[7] offset (floats)
#define W7OFF (7*8*4096)       // weights[7] offset (floats)

// Scratch (device globals — no allocations allowed)
__device__ float g_uhl[8*16384*64];  // [j][b][e] 32MB
__device__ float g_n2[8*16384];      // [j][b]
__device__ float g_um[512];          // sum_b u[b,i,d]
__device__ float g_uhm[4096];        // [i][j][e]
__device__ float g_B[64];
__device__ float g_t[512];           // [j][d]
__device__ float g_c[8];             // final-iteration c_j

__device__ __forceinline__ void fma2(ull &acc, ull a, ull b) {
    asm("fma.rn.f32x2 %0, %1, %2, %0;" : "+l"(acc) : "l"(a), "l"(b));
}
__device__ __forceinline__ ull pack2(float x) {
    unsigned u = __float_as_uint(x);
    ull r; asm("mov.b64 %0, {%1, %1};" : "=l"(r) : "r"(u)); return r;
}
__device__ __forceinline__ float2 unpack2(ull v) {
    unsigned lo, hi;
    asm("mov.b64 {%0, %1}, %2;" : "=r"(lo), "=r"(hi) : "l"(v));
    return make_float2(__uint_as_float(lo), __uint_as_float(hi));
}
__device__ __forceinline__ float squash_scal(float cj, float n2v) {
    float s2 = cj*cj*n2v;
    return cj*s2 / ((1.f+s2)*sqrtf(s2+1e-9f));
}
// x[7] memory row for u-row b:  u[b,7,d] = x[7, b&31, b>>5, d]
__device__ __forceinline__ int xrow(int b) {
    return (b & 31)*512 + (b >> 5);
}

__global__ void k_init() {
    int t = threadIdx.x;           // 512
    g_t[t] = 0.f; g_um[t] = 0.f;
    if (t < 64) g_B[t] = 0.f;
}

// sum over all 16384 rows of x[i] -> g_um[i*64+d]  (order-invariant)
__global__ void k_umean(const float* __restrict__ x) {
    __shared__ float red[4][64];
    int i = blockIdx.y, t = threadIdx.x, d = t & 63, g = t >> 6;
    const float* xp = x + i*1048576 + (blockIdx.x*1024 + g*256)*64 + d;
    float s = 0.f;
    #pragma unroll 4
    for (int m = 0; m < 256; m++) s += xp[m*64];
    red[g][d] = s;
    __syncthreads();
    if (t < 64) atomicAdd(&g_um[i*64+t], red[0][t]+red[1][t]+red[2][t]+red[3][t]);
}

// uhm[i,j,e] = sum_d W[i,j,d,e] * umean[i,d]
__global__ void k_uhm(const float* __restrict__ w) {
    __shared__ float um[512];
    int t = threadIdx.x;           // 256
    um[t]     = g_um[t]     * (1.f/16384.f);
    um[t+256] = g_um[t+256] * (1.f/16384.f);
    __syncthreads();
    #pragma unroll
    for (int o = 0; o < 16; o++) {
        int idx = t + 256*o;
        int i = idx >> 9, e = idx & 63;
        int ij = idx >> 6;         // i*8+j
        const float* wp = w + ij*4096 + e;
        const float* up = um + i*64;
        float s = 0.f;
        #pragma unroll 8
        for (int d = 0; d < 64; d++) s += wp[d*64] * up[d];
        g_uhm[idx] = s;
    }
}

// uhl[j,b,e] = sum_d u[b,7,d]*W7[j,d,e]; n2[j,b] = sum_e uhl^2
// 128 threads, 64 rows/block. W packed as natural col-pairs (f32x2),
// x broadcast-duplicated in registers. All LDS conflict-free.
// Thread (cg=t&7, rq=t>>3): rows 4rq..4rq+3, cols [4cg..4cg+3] u [32+4cg..+3].
__global__ __launch_bounds__(128) void k_gemm(const float* __restrict__ x,
                                              const float* __restrict__ w) {
    __shared__ float xs[64*64];    // [d][row] 16KB
    __shared__ float ws[64*64];    // [d][col] 16KB
    int t = threadIdx.x;           // 128
    int p0 = blockIdx.x * 64;      // b-block base

    {   // load + transpose 64 u-rows (gather from permuted x layout)
        int rp_ = t & 31, q = t >> 5;      // q: d-chunk of 16
        int bA = p0 + 2*rp_, bB = bA + 1;
        const float* pa = x + X7 + xrow(bA)*64 + q*16;
        const float* pb = x + X7 + xrow(bB)*64 + q*16;
        #pragma unroll
        for (int i = 0; i < 4; i++) {
            float4 a = *(const float4*)(pa + 4*i);
            float4 b = *(const float4*)(pb + 4*i);
            int d0 = q*16 + 4*i;
            xs[(d0+0)*64 + 2*rp_] = a.x; xs[(d0+0)*64 + 2*rp_+1] = b.x;
            xs[(d0+1)*64 + 2*rp_] = a.y; xs[(d0+1)*64 + 2*rp_+1] = b.y;
            xs[(d0+2)*64 + 2*rp_] = a.z; xs[(d0+2)*64 + 2*rp_+1] = b.z;
            xs[(d0+3)*64 + 2*rp_] = a.w; xs[(d0+3)*64 + 2*rp_+1] = b.w;
        }
    }

    int cg = t & 7, rq = t >> 3;
    int r0 = rq * 4;
    const float* W7p = w + W7OFF;

    for (int j = 0; j < 8; j++) {
        __syncthreads();
        #pragma unroll
        for (int k = 0; k < 8; k++) {   // fill W tile (natural layout)
            int idx = t + 128*k;
            *(float4*)(ws + idx*4) = *(const float4*)(W7p + j*4096 + idx*4);
        }
        __syncthreads();

        // acc[r][m]: m=0,1 -> cols 4cg..4cg+3 ; m=2,3 -> cols 32+4cg..+3
        ull acc[4][4];
        #pragma unroll
        for (int r = 0; r < 4; r++)
            #pragma unroll
            for (int m = 0; m < 4; m++) acc[r][m] = 0ULL;

        #pragma unroll 8
        for (int d = 0; d < 64; d++) {
            ulonglong2 w0 = *(const ulonglong2*)&ws[d*64 + cg*4];
            ulonglong2 w1 = *(const ulonglong2*)&ws[d*64 + 32 + cg*4];
            ull xr[4];
            #pragma unroll
            for (int r = 0; r < 4; r++) xr[r] = pack2(xs[d*64 + r0 + r]);
            #pragma unroll
            for (int r = 0; r < 4; r++) {
                fma2(acc[r][0], xr[r], w0.x);
                fma2(acc[r][1], xr[r], w0.y);
                fma2(acc[r][2], xr[r], w1.x);
                fma2(acc[r][3], xr[r], w1.y);
            }
        }

        #pragma unroll
        for (int r = 0; r < 4; r++) {
            float2 v0 = unpack2(acc[r][0]), v1 = unpack2(acc[r][1]);
            float2 v2 = unpack2(acc[r][2]), v3 = unpack2(acc[r][3]);
            int row = p0 + r0 + r;
            float* base = g_uhl + j*1048576 + row*64;
            *(float4*)(base + 4*cg)      = make_float4(v0.x, v0.y, v1.x, v1.y);
            *(float4*)(base + 32 + 4*cg) = make_float4(v2.x, v2.y, v3.x, v3.y);

            float s = v0.x*v0.x + v0.y*v0.y + v1.x*v1.x + v1.y*v1.y
                    + v2.x*v2.x + v2.y*v2.y + v3.x*v3.x + v3.y*v3.y;
            #pragma unroll
            for (int off = 1; off < 8; off <<= 1)
                s += __shfl_xor_sync(~0u, s, off);
            if (cg == 0) g_n2[j*16384 + row] = s;
        }
    }
}

// one routing reduction: c=softmax(B)[7,:]; t[j,d] += scal(b,j)*u[b,7,d]
__global__ __launch_bounds__(256) void k_route1(const float* __restrict__ x) {
    __shared__ float c_s[8];
    __shared__ float scal_s[256*8];
    __shared__ float red[4][512];
    int t = threadIdx.x;
    if (t < 8) {
        float m = g_B[t];
        #pragma unroll
        for (int i = 1; i < 8; i++) m = fmaxf(m, g_B[i*8+t]);
        float sum = 0.f, e7 = 0.f;
        #pragma unroll
        for (int i = 0; i < 8; i++) {
            float e = expf(g_B[i*8+t] - m);
            sum += e; if (i == 7) e7 = e;
        }
        c_s[t] = e7/sum;
    }
    __syncthreads();
    int p0 = blockIdx.x * 256;
    {
        int b = p0 + t;
        #pragma unroll
        for (int j = 0; j < 8; j++)
            scal_s[t*8+j] = squash_scal(c_s[j], g_n2[j*16384 + b]);
    }
    __syncthreads();
    int d = t & 63, g = t >> 6;
    float acc[8] = {0,0,0,0,0,0,0,0};
    for (int m = 0; m < 64; m++) {
        int r = g*64 + m;
        int b = p0 + r;
        float xv = x[X7 + xrow(b)*64 + d];
        #pragma unroll
        for (int j = 0; j < 8; j++) acc[j] += scal_s[r*8+j] * xv;
    }
    #pragma unroll
    for (int j = 0; j < 8; j++) red[g][j*64+d] = acc[j];
    __syncthreads();
    #pragma unroll
    for (int o = 0; o < 2; o++) {
        int idx = t + 256*o;
        atomicAdd(&g_t[idx], red[0][idx]+red[1][idx]+red[2][idx]+red[3][idx]);
    }
}

// vmean[j,e] = (1/16384)*sum_d W7[j,d,e]*t[j,d]; B += uhm.vmean; g_c=softmax(B)[7]
__global__ void k_route2(const float* __restrict__ w) {
    __shared__ float ts[512], vm[512];
    int t = threadIdx.x;           // 256
    ts[t] = g_t[t]; ts[t+256] = g_t[t+256];
    __syncthreads();
    g_t[t] = 0.f; g_t[t+256] = 0.f;
    const float* W7p = w + W7OFF;
    #pragma unroll
    for (int o = 0; o < 2; o++) {
        int idx = t + 256*o, j = idx >> 6, e = idx & 63;
        const float* wp = W7p + j*4096 + e;
        const float* tp = ts + j*64;
        float s = 0.f;
        #pragma unroll 8
        for (int d = 0; d < 64; d++) s += wp[d*64] * tp[d];
        vm[idx] = s * (1.f/16384.f);
    }
    __syncthreads();
    if (t < 64) {
        int j = t & 7;
        float s = 0.f;
        #pragma unroll 8
        for (int e = 0; e < 64; e++) s += g_uhm[t*64 + e] * vm[j*64 + e];
        g_B[t] += s;
    }
    __syncthreads();
    if (t < 8) {
        float m = g_B[t];
        #pragma unroll
        for (int i = 1; i < 8; i++) m = fmaxf(m, g_B[i*8+t]);
        float sum = 0.f, e7 = 0.f;
        #pragma unroll
        for (int i = 0; i < 8; i++) {
            float e = expf(g_B[i*8+t] - m);
            sum += e; if (i == 7) e7 = e;
        }
        g_c[t] = e7/sum;
    }
}

// out[j,b,e] = scal3(j,b) * uhl[j,b,e]  (pure stream; output position == b)
__global__ void k_out(float* __restrict__ out) {
    __shared__ float scal_s[128];
    int j = blockIdx.y, p0 = blockIdx.x * 128, t = threadIdx.x;
    if (t < 128) scal_s[t] = squash_scal(g_c[j], g_n2[j*16384 + p0 + t]);
    __syncthreads();
    const float4* src = (const float4*)(g_uhl + j*1048576 + p0*64);
    float4* dst = (float4*)(out + j*1048576 + p0*64);
    #pragma unroll
    for (int k = 0; k < 8; k++) {
        int idx = k*256 + t;       // 2048 float4
        float4 v = src[idx];
        float s = scal_s[idx >> 4];
        v.x *= s; v.y *= s; v.z *= s; v.w *= s;
        dst[idx] = v;
    }
}

extern "C" void kernel_launch(void* const* d_in, const int* in_sizes, int n_in,
                              void* d_out, int out_size) {
    const float* x = (const float*)d_in[0];
    const float* w = (const float*)d_in[1];
    float* out = (float*)d_out;
    k_init<<<1, 512>>>();
    k_umean<<<dim3(16, 8), 256>>>(x);
    k_uhm<<<1, 256>>>(w);
    k_gemm<<<256, 128>>>(x, w);
    k_route1<<<64, 256>>>(x);
    k_route2<<<1, 256>>>(w);
    k_route1<<<64, 256>>>(x);
    k_route2<<<1, 256>>>(w);
    k_out<<<dim3(128, 8), 256>>>(out);
}

// round 6
// speedup vs baseline: 4.3764x; 1.9127x over previous
#include <cuda_runtime.h>

typedef unsigned long long ull;

#define X7    (7*1048576)      // x[7] offset (floats)
#define W7OFF (7*8*4096)       // weights[7] offset (floats)

// Scratch (device globals — no allocations allowed)
__device__ float g_uhl[8*16384*64];  // [j][b][e] 32MB
__device__ float g_n2[8*16384];      // [j][b]
__device__ float g_um[512];          // sum_b u[b,i,d]
__device__ float g_uhm[4096];        // [i][j][e]
__device__ float g_B[64];
__device__ float g_t[512];           // [j][d]
__device__ float g_c[8];             // final-iteration c_j

__device__ __forceinline__ void fma2(ull &acc, ull a, ull b) {
    asm("fma.rn.f32x2 %0, %1, %2, %0;" : "+l"(acc) : "l"(a), "l"(b));
}
__device__ __forceinline__ ull pack2(float x) {
    unsigned u = __float_as_uint(x);
    ull r; asm("mov.b64 %0, {%1, %1};" : "=l"(r) : "r"(u)); return r;
}
__device__ __forceinline__ float2 unpack2(ull v) {
    unsigned lo, hi;
    asm("mov.b64 {%0, %1}, %2;" : "=r"(lo), "=r"(hi) : "l"(v));
    return make_float2(__uint_as_float(lo), __uint_as_float(hi));
}
__device__ __forceinline__ float squash_scal(float cj, float n2v) {
    float s2 = cj*cj*n2v;
    return cj*s2 / ((1.f+s2)*sqrtf(s2+1e-9f));
}
// x[7] memory row for u-row b:  u[b,7,d] = x[7, b&31, b>>5, d]
__device__ __forceinline__ int xrow(int b) {
    return (b & 31)*512 + (b >> 5);
}

__global__ void k_init() {
    int t = threadIdx.x;           // 512
    g_t[t] = 0.f; g_um[t] = 0.f;
    if (t < 64) g_B[t] = 0.f;
}

// sum over all 16384 rows of x[i] -> g_um[i*64+d]. float4 loads, MLP 8.
__global__ __launch_bounds__(256) void k_umean(const float* __restrict__ x) {
    __shared__ float4 red[16][16];
    int i = blockIdx.y, t = threadIdx.x;
    int dq = (t & 15) * 4, g = t >> 4;          // 16 d-quads, 16 row-groups
    const float* xp = x + i*1048576 + (blockIdx.x*512 + g*32)*64 + dq;
    float4 acc = make_float4(0.f,0.f,0.f,0.f);
    #pragma unroll 8
    for (int m = 0; m < 32; m++) {
        float4 v = *(const float4*)(xp + m*64);
        acc.x += v.x; acc.y += v.y; acc.z += v.z; acc.w += v.w;
    }
    red[g][t & 15] = acc;
    __syncthreads();
    if (t < 16) {
        float4 s = make_float4(0.f,0.f,0.f,0.f);
        #pragma unroll
        for (int gg = 0; gg < 16; gg++) {
            float4 v = red[gg][t];
            s.x += v.x; s.y += v.y; s.z += v.z; s.w += v.w;
        }
        atomicAdd(&g_um[i*64 + t*4 + 0], s.x);
        atomicAdd(&g_um[i*64 + t*4 + 1], s.y);
        atomicAdd(&g_um[i*64 + t*4 + 2], s.z);
        atomicAdd(&g_um[i*64 + t*4 + 3], s.w);
    }
}

// uhm[i,j,e] = sum_d W[i,j,d,e] * umean[i,d]   (16 blocks x 4 ij each)
__global__ __launch_bounds__(256) void k_uhm(const float* __restrict__ w) {
    __shared__ float um[512];
    int t = threadIdx.x;           // 256
    um[t]     = g_um[t]     * (1.f/16384.f);
    um[t+256] = g_um[t+256] * (1.f/16384.f);
    __syncthreads();
    int ij = blockIdx.x*4 + (t >> 6), e = t & 63;
    int i = ij >> 3;
    const float* wp = w + ij*4096 + e;
    const float* up = um + i*64;
    float s = 0.f;
    #pragma unroll 8
    for (int d = 0; d < 64; d++) s += wp[d*64] * up[d];
    g_uhm[ij*64 + e] = s;
}

// uhl[j,b,e] = sum_d u[b,7,d]*W7[j,d,e]; n2[j,b] = sum_e uhl^2
// grid (256 p-blocks, 2 j-groups); 64 rows/block, 4 j per block.
__global__ __launch_bounds__(128) void k_gemm(const float* __restrict__ x,
                                              const float* __restrict__ w) {
    __shared__ float xs[64*64];    // [d][row] 16KB
    __shared__ float ws[64*64];    // [d][col] 16KB
    int t = threadIdx.x;           // 128
    int p0 = blockIdx.x * 64;      // b-block base
    int j0 = blockIdx.y * 4;

    {   // load + transpose 64 u-rows (gather from permuted x layout)
        int rp_ = t & 31, q = t >> 5;      // q: d-chunk of 16
        int bA = p0 + 2*rp_, bB = bA + 1;
        const float* pa = x + X7 + xrow(bA)*64 + q*16;
        const float* pb = x + X7 + xrow(bB)*64 + q*16;
        #pragma unroll
        for (int i = 0; i < 4; i++) {
            float4 a = *(const float4*)(pa + 4*i);
            float4 b = *(const float4*)(pb + 4*i);
            int d0 = q*16 + 4*i;
            xs[(d0+0)*64 + 2*rp_] = a.x; xs[(d0+0)*64 + 2*rp_+1] = b.x;
            xs[(d0+1)*64 + 2*rp_] = a.y; xs[(d0+1)*64 + 2*rp_+1] = b.y;
            xs[(d0+2)*64 + 2*rp_] = a.z; xs[(d0+2)*64 + 2*rp_+1] = b.z;
            xs[(d0+3)*64 + 2*rp_] = a.w; xs[(d0+3)*64 + 2*rp_+1] = b.w;
        }
    }

    int cg = t & 7, rq = t >> 3;
    int r0 = rq * 4;
    const float* W7p = w + W7OFF;

    for (int jj = 0; jj < 4; jj++) {
        int j = j0 + jj;
        __syncthreads();
        #pragma unroll
        for (int k = 0; k < 8; k++) {   // fill W tile (natural layout)
            int idx = t + 128*k;
            *(float4*)(ws + idx*4) = *(const float4*)(W7p + j*4096 + idx*4);
        }
        __syncthreads();

        // acc[r][m]: m=0,1 -> cols 4cg..4cg+3 ; m=2,3 -> cols 32+4cg..+3
        ull acc[4][4];
        #pragma unroll
        for (int r = 0; r < 4; r++)
            #pragma unroll
            for (int m = 0; m < 4; m++) acc[r][m] = 0ULL;

        #pragma unroll 8
        for (int d = 0; d < 64; d++) {
            ulonglong2 w0 = *(const ulonglong2*)&ws[d*64 + cg*4];
            ulonglong2 w1 = *(const ulonglong2*)&ws[d*64 + 32 + cg*4];
            ull xr[4];
            #pragma unroll
            for (int r = 0; r < 4; r++) xr[r] = pack2(xs[d*64 + r0 + r]);
            #pragma unroll
            for (int r = 0; r < 4; r++) {
                fma2(acc[r][0], xr[r], w0.x);
                fma2(acc[r][1], xr[r], w0.y);
                fma2(acc[r][2], xr[r], w1.x);
                fma2(acc[r][3], xr[r], w1.y);
            }
        }

        #pragma unroll
        for (int r = 0; r < 4; r++) {
            float2 v0 = unpack2(acc[r][0]), v1 = unpack2(acc[r][1]);
            float2 v2 = unpack2(acc[r][2]), v3 = unpack2(acc[r][3]);
            int row = p0 + r0 + r;
            float* base = g_uhl + j*1048576 + row*64;
            *(float4*)(base + 4*cg)      = make_float4(v0.x, v0.y, v1.x, v1.y);
            *(float4*)(base + 32 + 4*cg) = make_float4(v2.x, v2.y, v3.x, v3.y);

            float s = v0.x*v0.x + v0.y*v0.y + v1.x*v1.x + v1.y*v1.y
                    + v2.x*v2.x + v2.y*v2.y + v3.x*v3.x + v3.y*v3.y;
            #pragma unroll
            for (int off = 1; off < 8; off <<= 1)
                s += __shfl_xor_sync(~0u, s, off);
            if (cg == 0) g_n2[j*16384 + row] = s;
        }
    }
}

// one routing reduction: c=softmax(B)[7,:]; t[j,d] += scal(b,j)*u[b,7,d]
__global__ __launch_bounds__(256) void k_route1(const float* __restrict__ x) {
    __shared__ float c_s[8];
    __shared__ float scal_s[256*8];
    __shared__ float red[4][512];
    int t = threadIdx.x;
    if (t < 8) {
        float m = g_B[t];
        #pragma unroll
        for (int i = 1; i < 8; i++) m = fmaxf(m, g_B[i*8+t]);
        float sum = 0.f, e7 = 0.f;
        #pragma unroll
        for (int i = 0; i < 8; i++) {
            float e = expf(g_B[i*8+t] - m);
            sum += e; if (i == 7) e7 = e;
        }
        c_s[t] = e7/sum;
    }
    __syncthreads();
    int p0 = blockIdx.x * 256;
    {
        int b = p0 + t;
        #pragma unroll
        for (int j = 0; j < 8; j++)
            scal_s[t*8+j] = squash_scal(c_s[j], g_n2[j*16384 + b]);
    }
    __syncthreads();
    int d = t & 63, g = t >> 6;
    float acc[8] = {0,0,0,0,0,0,0,0};
    #pragma unroll 8
    for (int m = 0; m < 64; m++) {
        int r = g*64 + m;
        int b = p0 + r;
        float xv = x[X7 + xrow(b)*64 + d];
        #pragma unroll
        for (int j = 0; j < 8; j++) acc[j] += scal_s[r*8+j] * xv;
    }
    #pragma unroll
    for (int j = 0; j < 8; j++) red[g][j*64+d] = acc[j];
    __syncthreads();
    #pragma unroll
    for (int o = 0; o < 2; o++) {
        int idx = t + 256*o;
        atomicAdd(&g_t[idx], red[0][idx]+red[1][idx]+red[2][idx]+red[3][idx]);
    }
}

// vmean[j,e] = (1/16384)*sum_d W7[j,d,e]*t[j,d]; B += uhm.vmean; g_c=softmax(B)[7]
__global__ void k_route2(const float* __restrict__ w) {
    __shared__ float ts[512], vm[512];
    int t = threadIdx.x;           // 256
    ts[t] = g_t[t]; ts[t+256] = g_t[t+256];
    __syncthreads();
    g_t[t] = 0.f; g_t[t+256] = 0.f;
    const float* W7p = w + W7OFF;
    #pragma unroll
    for (int o = 0; o < 2; o++) {
        int idx = t + 256*o, j = idx >> 6, e = idx & 63;
        const float* wp = W7p + j*4096 + e;
        const float* tp = ts + j*64;
        float s = 0.f;
        #pragma unroll 8
        for (int d = 0; d < 64; d++) s += wp[d*64] * tp[d];
        vm[idx] = s * (1.f/16384.f);
    }
    __syncthreads();
    if (t < 64) {
        int j = t & 7;
        float s = 0.f;
        #pragma unroll 8
        for (int e = 0; e < 64; e++) s += g_uhm[t*64 + e] * vm[j*64 + e];
        g_B[t] += s;
    }
    __syncthreads();
    if (t < 8) {
        float m = g_B[t];
        #pragma unroll
        for (int i = 1; i < 8; i++) m = fmaxf(m, g_B[i*8+t]);
        float sum = 0.f, e7 = 0.f;
        #pragma unroll
        for (int i = 0; i < 8; i++) {
            float e = expf(g_B[i*8+t] - m);
            sum += e; if (i == 7) e7 = e;
        }
        g_c[t] = e7/sum;
    }
}

// out[j,b,e] = scal3(j,b) * uhl[j,b,e]  (pure stream; output position == b)
__global__ void k_out(float* __restrict__ out) {
    __shared__ float scal_s[128];
    int j = blockIdx.y, p0 = blockIdx.x * 128, t = threadIdx.x;
    if (t < 128) scal_s[t] = squash_scal(g_c[j], g_n2[j*16384 + p0 + t]);
    __syncthreads();
    const float4* src = (const float4*)(g_uhl + j*1048576 + p0*64);
    float4* dst = (float4*)(out + j*1048576 + p0*64);
    #pragma unroll
    for (int k = 0; k < 8; k++) {
        int idx = k*256 + t;       // 2048 float4
        float4 v = src[idx];
        float s = scal_s[idx >> 4];
        v.x *= s; v.y *= s; v.z *= s; v.w *= s;
        dst[idx] = v;
    }
}

extern "C" void kernel_launch(void* const* d_in, const int* in_sizes, int n_in,
                              void* d_out, int out_size) {
    const float* x = (const float*)d_in[0];
    const float* w = (const float*)d_in[1];
    float* out = (float*)d_out;
    k_init<<<1, 512>>>();
    k_umean<<<dim3(32, 8), 256>>>(x);
    k_uhm<<<16, 256>>>(w);
    k_gemm<<<dim3(256, 2), 128>>>(x, w);
    k_route1<<<64, 256>>>(x);
    k_route2<<<1, 256>>>(w);
    k_route1<<<64, 256>>>(x);
    k_route2<<<1, 256>>>(w);
    k_out<<<dim3(128, 8), 256>>>(out);
}